// round 7
// baseline (speedup 1.0000x reference)
#include <cuda_runtime.h>
#include <cuda_bf16.h>
#include <cstddef>

// EMA: out[b,t,c] = 0.1*x + 0.9*out[b,t-1,c], out[b,0,c]=x[b,0,c].
// (16, 4096, 512) fp32. Time-parallel truncated lookback (0.9^128 ~ 1.4e-6).
//
// R6 -> R7: fix SM load imbalance. 512 blocks on 148 SMs gave a 4-vs-3
// blocks/SM split (~16% tail). Now 1024 one-warp blocks (float2 lanes,
// 64 channels/warp) -> 7-vs-6.92 split (~1% tail). Main loop unrolled x32
// for 8KB in-flight per warp. Streaming stores retained.

namespace {
constexpr int B = 16;
constexpr int T = 4096;
constexpr int C = 512;
constexpr int C2 = C / 2;             // 256 float2 columns
constexpr int SEG_LEN = 512;
constexpr int NSEG = T / SEG_LEN;     // 8
constexpr int LOOKBACK = 128;         // 0.9^128 ~ 1.4e-6
constexpr int BLOCK_THREADS = 32;     // 1 warp, 64 channels
constexpr float ALPHA = 0.1f;
constexpr float BETA  = 0.9f;
}

__global__ __launch_bounds__(BLOCK_THREADS, 32)
void ema_lookback_v3_kernel(const float2* __restrict__ x, float2* __restrict__ out) {
    const int c2  = blockIdx.x * BLOCK_THREADS + threadIdx.x;  // float2 column
    const int seg = blockIdx.y;
    const int b   = blockIdx.z;

    const size_t base = (size_t)b * T * C2 + (size_t)c2;
    const float2* __restrict__ xp = x   + base;
    float2*       __restrict__ op = out + base;

    const int t0 = seg * SEG_LEN;
    float2 y;
    int tstart;

    if (seg == 0) {
        y = xp[0];
        __stcs(&op[0], y);
        tstart = 1;
    } else {
        // Warm-up from zero init over LOOKBACK steps (no stores).
        y.x = 0.0f; y.y = 0.0f;
        const int tl = t0 - LOOKBACK;
        #pragma unroll 32
        for (int k = 0; k < LOOKBACK; ++k) {
            const float2 xv = xp[(size_t)(tl + k) * C2];
            y.x = fmaf(BETA, y.x, ALPHA * xv.x);
            y.y = fmaf(BETA, y.y, ALPHA * xv.y);
        }
        tstart = t0;
    }

    const int tend = t0 + SEG_LEN;
    #pragma unroll 32
    for (int t = tstart; t < tend; ++t) {
        const float2 xv = xp[(size_t)t * C2];
        y.x = fmaf(BETA, y.x, ALPHA * xv.x);
        y.y = fmaf(BETA, y.y, ALPHA * xv.y);
        __stcs(&op[(size_t)t * C2], y);   // write-once, never read
    }
}

extern "C" void kernel_launch(void* const* d_in, const int* in_sizes, int n_in,
                              void* d_out, int out_size) {
    (void)in_sizes; (void)n_in; (void)out_size;
    const float2* x = (const float2*)d_in[0];
    float2* out = (float2*)d_out;

    dim3 grid(C2 / BLOCK_THREADS, NSEG, B);  // (8, 8, 16) = 1024 blocks
    dim3 block(BLOCK_THREADS);               // 32 threads (1 warp)
    ema_lookback_v3_kernel<<<grid, block>>>(x, out);
}

// round 10
// speedup vs baseline: 1.1163x; 1.1163x over previous
#include <cuda_runtime.h>
#include <cuda_bf16.h>
#include <cstddef>

// EMA: out[b,t,c] = 0.1*x + 0.9*out[b,t-1,c], out[b,0,c]=x[b,0,c].
// (16, 4096, 512) fp32. Time-parallel truncated lookback (0.9^128 ~ 1.4e-6).
//
// R7 -> R8: scalar float (2048 warps, max parallelism — R5's best config),
// plus EXPLICIT 32-wide load batching: all 32 LDGs of a batch issue before
// the dependent FMA/store chain, forcing MLP_eff ~ 32 (vs ~8 when ptxas
// interleaves). In-flight bytes ~8MB chip-wide vs the ~2MB Little's-law
// knee that pinned DRAM at ~60% in R5-R7. 64-thread blocks for fine
// scheduling granularity. Streaming stores retained.

namespace {
constexpr int B = 16;
constexpr int T = 4096;
constexpr int C = 512;
constexpr int SEG_LEN = 512;
constexpr int NSEG = T / SEG_LEN;     // 8
constexpr int LOOKBACK = 128;         // 0.9^128 ~ 1.4e-6
constexpr int BLOCK_THREADS = 64;     // 2 warps
constexpr int BATCH = 32;             // explicit load batch (MLP)
constexpr float ALPHA = 0.1f;
constexpr float BETA  = 0.9f;
}

__global__ __launch_bounds__(BLOCK_THREADS, 24)
void ema_lookback_v4_kernel(const float* __restrict__ x, float* __restrict__ out) {
    const int c   = blockIdx.x * BLOCK_THREADS + threadIdx.x;  // channel
    const int seg = blockIdx.y;
    const int b   = blockIdx.z;

    const size_t base = (size_t)b * T * C + (size_t)c;
    const float* __restrict__ xp = x   + base;
    float*       __restrict__ op = out + base;

    const int t0 = seg * SEG_LEN;
    float y;

    if (seg == 0) {
        // Seed so the t=0 step reproduces out[0] = x[0]:
        // fma(0.9, x0, 0.1*x0) == x0 up to 1 ulp.
        y = xp[0];
    } else {
        // Warm-up from zero init over LOOKBACK steps, batched loads.
        y = 0.0f;
        const int tl = t0 - LOOKBACK;
        #pragma unroll
        for (int tb = 0; tb < LOOKBACK; tb += BATCH) {
            float xv[BATCH];
            #pragma unroll
            for (int i = 0; i < BATCH; ++i)
                xv[i] = xp[(size_t)(tl + tb + i) * C];
            #pragma unroll
            for (int i = 0; i < BATCH; ++i)
                y = fmaf(BETA, y, ALPHA * xv[i]);
        }
    }

    // Main segment: 512 steps, 32-batched. All BATCH loads issue before the
    // dependent FMA/store chain consumes them.
    for (int tb = t0; tb < t0 + SEG_LEN; tb += BATCH) {
        float xv[BATCH];
        #pragma unroll
        for (int i = 0; i < BATCH; ++i)
            xv[i] = xp[(size_t)(tb + i) * C];
        #pragma unroll
        for (int i = 0; i < BATCH; ++i) {
            y = fmaf(BETA, y, ALPHA * xv[i]);
            __stcs(&op[(size_t)(tb + i) * C], y);  // write-once, never read
        }
    }
}

extern "C" void kernel_launch(void* const* d_in, const int* in_sizes, int n_in,
                              void* d_out, int out_size) {
    (void)in_sizes; (void)n_in; (void)out_size;
    const float* x = (const float*)d_in[0];
    float* out = (float*)d_out;

    dim3 grid(C / BLOCK_THREADS, NSEG, B);   // (8, 8, 16) = 1024 blocks
    dim3 block(BLOCK_THREADS);               // 64 threads (2 warps)
    ema_lookback_v4_kernel<<<grid, block>>>(x, out);
}

// round 11
// speedup vs baseline: 1.1400x; 1.0212x over previous
#include <cuda_runtime.h>
#include <cuda_bf16.h>
#include <cstddef>

// EMA: out[b,t,c] = 0.1*x + 0.9*out[b,t-1,c], out[b,0,c]=x[b,0,c].
// (16, 4096, 512) fp32. Time-parallel truncated lookback (0.9^128 ~ 1.4e-6).
//
// R8 -> R11: DRAM row-locality restructure. Previous layouts gave each
// block a 128-256B slice of every 2KB t-row => every HBM access was a
// row-buffer miss (DRAM% pinned ~62% across 4 configs, invariant to
// warps/MLP). Now ONE block owns one (b,seg) tile and ALL 512 channels:
// 256 threads x float2 read the full contiguous 2KB row per t, consecutive
// t are adjacent => the block's aggregate load AND store streams are purely
// sequential. 16-deep t-batching for MLP (32KB in flight/SM).

namespace {
constexpr int B = 16;
constexpr int T = 4096;
constexpr int C = 512;
constexpr int C2 = C / 2;             // 256 float2 columns
constexpr int SEG_LEN = 512;
constexpr int NSEG = T / SEG_LEN;     // 8
constexpr int LOOKBACK = 128;         // 0.9^128 ~ 1.4e-6
constexpr int THREADS = 256;          // = C2: one float2 column per thread
constexpr int BT = 16;                // t-steps batched per iteration (MLP)
constexpr float ALPHA = 0.1f;
constexpr float BETA  = 0.9f;
}

__global__ __launch_bounds__(THREADS, 4)
void ema_rowloc_kernel(const float2* __restrict__ x, float2* __restrict__ out) {
    const int seg = blockIdx.x & (NSEG - 1);
    const int b   = blockIdx.x >> 3;           // NSEG == 8
    const int c2  = threadIdx.x;               // 0..255

    const size_t base = (size_t)b * T * C2 + (size_t)c2;
    const float2* __restrict__ xp = x   + base;
    float2*       __restrict__ op = out + base;

    const int t0 = seg * SEG_LEN;
    float2 y;

    if (seg == 0) {
        // Seed so the t=0 step reproduces out[0] = x[0]:
        // fma(0.9, x0, 0.1*x0) == x0 up to 1 ulp.
        y = xp[0];
    } else {
        // Warm-up from zero init over LOOKBACK steps, BT-batched loads.
        y.x = 0.0f; y.y = 0.0f;
        const int tl = t0 - LOOKBACK;
        #pragma unroll
        for (int tb = 0; tb < LOOKBACK; tb += BT) {
            float2 xv[BT];
            #pragma unroll
            for (int i = 0; i < BT; ++i)
                xv[i] = xp[(size_t)(tl + tb + i) * C2];
            #pragma unroll
            for (int i = 0; i < BT; ++i) {
                y.x = fmaf(BETA, y.x, ALPHA * xv[i].x);
                y.y = fmaf(BETA, y.y, ALPHA * xv[i].y);
            }
        }
    }

    // Main segment: 512 steps, BT-batched. All BT loads issue before the
    // dependent FMA/store chain consumes them.
    #pragma unroll 1
    for (int tb = t0; tb < t0 + SEG_LEN; tb += BT) {
        float2 xv[BT];
        #pragma unroll
        for (int i = 0; i < BT; ++i)
            xv[i] = xp[(size_t)(tb + i) * C2];
        #pragma unroll
        for (int i = 0; i < BT; ++i) {
            y.x = fmaf(BETA, y.x, ALPHA * xv[i].x);
            y.y = fmaf(BETA, y.y, ALPHA * xv[i].y);
            __stcs(&op[(size_t)(tb + i) * C2], y);  // write-once, never read
        }
    }
}

extern "C" void kernel_launch(void* const* d_in, const int* in_sizes, int n_in,
                              void* d_out, int out_size) {
    (void)in_sizes; (void)n_in; (void)out_size;
    const float2* x = (const float2*)d_in[0];
    float2* out = (float2*)d_out;

    dim3 grid(B * NSEG);     // 128 blocks, each owns a contiguous (b,seg) tile
    dim3 block(THREADS);     // 256 threads (8 warps)
    ema_rowloc_kernel<<<grid, block>>>(x, out);
}